// round 15
// baseline (speedup 1.0000x reference)
#include <cuda_runtime.h>
#include <math.h>
#include <stdint.h>

#define S_LEN 2048
#define E_DIM 512
#define H_DIM 512
#define G3    1536   // 3*H
#define F2    1024   // 2*H
#define CLN   16     // CTAs per direction (one cluster)
#define TFS   132    // tf32 smem row stride in ull (conflict-free frag loads)

typedef unsigned long long ull;

// ---------------- device scratch (static; no allocations) ----------------
__device__ float g_gx[4][S_LEN * G3];
__device__ float g_feat[2][S_LEN * F2];      // 0: src bi-feat, 1: tgt bi-feat
__device__ float g_attn[2][S_LEN * S_LEN];   // 0: cross align, 1: self align
__device__ float g_ctx2[2][S_LEN * F2];      // 0: context, 1: s_context
__device__ float g_emit[S_LEN * 2];
// pre-split (hi,lo) tf32 operand buffers
__device__ ull g_sxt[2][S_LEN * E_DIM];      // split source / target
__device__ ull g_swih[4][G3 * E_DIM];        // split Wih per dir
__device__ ull g_sfeat[2][S_LEN * F2];       // split feat
__device__ ull g_sattn[2][S_LEN * S_LEN];    // split softmaxed attention

// ---------------- helpers ----------------
__device__ __forceinline__ uint32_t smem_u32(const void* p) {
    uint32_t a;
    asm("{ .reg .u64 t; cvta.to.shared.u64 t, %1; cvt.u32.u64 %0, t; }" : "=r"(a) : "l"(p));
    return a;
}
__device__ __forceinline__ uint32_t mapa_rank(uint32_t laddr, uint32_t rank) {
    uint32_t r;
    asm("mapa.shared::cluster.u32 %0, %1, %2;" : "=r"(r) : "r"(laddr), "r"(rank));
    return r;
}
__device__ __forceinline__ void st_cluster_f32(uint32_t addr, float v) {
    asm volatile("st.shared::cluster.f32 [%0], %1;" :: "r"(addr), "f"(v) : "memory");
}
#define CLUSTER_ARRIVE() asm volatile("barrier.cluster.arrive.aligned;" ::: "memory")
#define CLUSTER_WAIT()   asm volatile("barrier.cluster.wait.aligned;" ::: "memory")
#define CLUSTER_BAR() do { CLUSTER_ARRIVE(); CLUSTER_WAIT(); } while (0)

__device__ __forceinline__ float warp_max(float x) {
#pragma unroll
    for (int o = 16; o > 0; o >>= 1) x = fmaxf(x, __shfl_xor_sync(0xffffffffu, x, o));
    return x;
}
__device__ __forceinline__ float warp_sum(float x) {
#pragma unroll
    for (int o = 16; o > 0; o >>= 1) x += __shfl_xor_sync(0xffffffffu, x, o);
    return x;
}
__device__ __forceinline__ float fsig(float x) {
    return __fdividef(1.f, 1.f + __expf(-x));
}
__device__ __forceinline__ float ftanh(float x) {
    float t = __expf(2.f * x);
    return 1.f - __fdividef(2.f, t + 1.f);
}
__device__ __forceinline__ float lse2(float a, float b) {
    float m = fmaxf(a, b);
    float d = fminf(a, b) - m;
    return m + __logf(1.f + __expf(d));
}
// split v = hi + lo (both tf32-representable), packed hi=low32, lo=high32
__device__ __forceinline__ ull pack_tf32(float v) {
    uint32_t hi, lo;
    asm("cvt.rna.tf32.f32 %0, %1;" : "=r"(hi) : "f"(v));
    float lof = v - __uint_as_float(hi);
    asm("cvt.rna.tf32.f32 %0, %1;" : "=r"(lo) : "f"(lof));
    return (ull)hi | ((ull)lo << 32);
}
#define MMA_TF32_K8(d, A0, A1, A2, A3, B0, B1) \
    asm("mma.sync.aligned.m16n8k8.row.col.f32.tf32.tf32.f32 " \
        "{%0,%1,%2,%3}, {%4,%5,%6,%7}, {%8,%9}, {%0,%1,%2,%3};" \
        : "+f"((d)[0]), "+f"((d)[1]), "+f"((d)[2]), "+f"((d)[3]) \
        : "r"(A0), "r"(A1), "r"(A2), "r"(A3), "r"(B0), "r"(B1))

// ---------------- split kernel: float -> packed (hi,lo) tf32 ull ----------------
__global__ void __launch_bounds__(256) split_kernel(
    const float* __restrict__ in, ull* __restrict__ out, int n)
{
    int i = (blockIdx.x * 256 + threadIdx.x) * 4;
    if (i < n) {
        float4 v = *(const float4*)(in + i);
        ulonglong2 o0, o1;
        o0.x = pack_tf32(v.x); o0.y = pack_tf32(v.y);
        o1.x = pack_tf32(v.z); o1.y = pack_tf32(v.w);
        *(ulonglong2*)(out + i)     = o0;
        *(ulonglong2*)(out + i + 2) = o1;
    }
}

// ---------------- batched 3xTF32 tensor-core GEMM (m16n8k8, pre-split) -------
// C[M,N] = alpha * A[M,K] * op(B) (+ bias[n]). A,B are PRE-SPLIT ull buffers.
// TB=1: B is [N,K]; TB=0: [K,N]. acc += Ah*Bl + Al*Bh + Ah*Bh.
// CTA 128x128, 8 warps (2Mx4N), warp tile 64x32, double-buffered smem.
// Mainloop has NO conversion math: LDG.128 -> STS -> LDS.64 -> MMA.
struct GemmEnt { const ull* A; const ull* B; float* C; const float* bias; };
struct GemmBatch4 { GemmEnt g[4]; };

template <int TB>
__global__ void __launch_bounds__(256, 1) tf32gemm_kernel(
    GemmBatch4 bt, int M, int N, int K, float alpha)
{
    const ull* __restrict__ A      = bt.g[blockIdx.z].A;
    const ull* __restrict__ B      = bt.g[blockIdx.z].B;
    float* __restrict__ C          = bt.g[blockIdx.z].C;
    const float* __restrict__ bias = bt.g[blockIdx.z].bias;

    __shared__ ull Ab[2][8][TFS];
    __shared__ ull Bb[2][8][TFS];

    int tid  = threadIdx.x;
    int lane = tid & 31, w = tid >> 5;
    int g = lane >> 2, t = lane & 3;
    int mbase = (w >> 2) * 64;
    int nbase = (w & 3) * 32;
    int m0 = blockIdx.y * 128, n0 = blockIdx.x * 128;

    float acc[4][4][4];
#pragma unroll
    for (int mt = 0; mt < 4; mt++)
#pragma unroll
        for (int nt = 0; nt < 4; nt++)
#pragma unroll
            for (int q = 0; q < 4; q++) acc[mt][nt][q] = 0.f;

    int lr = tid >> 1;            // 0..127
    int lc = (tid & 1) * 4;       // 0 or 4
    const ull* Aptr = A + (size_t)(m0 + lr) * K + lc;
    const ull* Bptr;
    int br = tid >> 5;            // 0..7 (k row, TB=0)
    int bc = (tid & 31) << 2;     // n col, TB=0
    if (TB) Bptr = B + (size_t)(n0 + lr) * K + lc;
    else    Bptr = B + (size_t)br * N + n0 + bc;

    // preload tile 0
    {
        ulonglong2 a01 = *(const ulonglong2*)(Aptr);
        ulonglong2 a23 = *(const ulonglong2*)(Aptr + 2);
        Ab[0][lc + 0][lr] = a01.x; Ab[0][lc + 1][lr] = a01.y;
        Ab[0][lc + 2][lr] = a23.x; Ab[0][lc + 3][lr] = a23.y;
        ulonglong2 b01 = *(const ulonglong2*)(Bptr);
        ulonglong2 b23 = *(const ulonglong2*)(Bptr + 2);
        if (TB) {
            Bb[0][lc + 0][lr] = b01.x; Bb[0][lc + 1][lr] = b01.y;
            Bb[0][lc + 2][lr] = b23.x; Bb[0][lc + 3][lr] = b23.y;
        } else {
            *(ulonglong2*)&Bb[0][br][bc]     = b01;
            *(ulonglong2*)&Bb[0][br][bc + 2] = b23;
        }
    }
    __syncthreads();

    int buf = 0;
    for (int k0 = 0; k0 < K; k0 += 8) {
        bool hasnext = (k0 + 8 < K);
        ulonglong2 a01, a23, b01, b23;
        if (hasnext) {
            a01 = *(const ulonglong2*)(Aptr + k0 + 8);
            a23 = *(const ulonglong2*)(Aptr + k0 + 10);
            if (TB) {
                b01 = *(const ulonglong2*)(Bptr + k0 + 8);
                b23 = *(const ulonglong2*)(Bptr + k0 + 10);
            } else {
                b01 = *(const ulonglong2*)(Bptr + (size_t)(k0 + 8) * N);
                b23 = *(const ulonglong2*)(Bptr + (size_t)(k0 + 8) * N + 2);
            }
        }

        // hoist ALL fragments for this k-tile into registers
        uint32_t ah[4][4], al[4][4], bh[4][2], bl[4][2];
#pragma unroll
        for (int nt = 0; nt < 4; nt++) {
            int c = nbase + nt * 8 + g;
            ull v0 = Bb[buf][t][c];
            ull v1 = Bb[buf][t + 4][c];
            bh[nt][0] = (uint32_t)v0; bl[nt][0] = (uint32_t)(v0 >> 32);
            bh[nt][1] = (uint32_t)v1; bl[nt][1] = (uint32_t)(v1 >> 32);
        }
#pragma unroll
        for (int mt = 0; mt < 4; mt++) {
            int r = mbase + mt * 16 + g;
            ull u0 = Ab[buf][t][r];          // a0=(g,   t)
            ull u1 = Ab[buf][t][r + 8];      // a1=(g+8, t)
            ull u2 = Ab[buf][t + 4][r];      // a2=(g,   t+4)
            ull u3 = Ab[buf][t + 4][r + 8];  // a3=(g+8, t+4)
            ah[mt][0] = (uint32_t)u0; al[mt][0] = (uint32_t)(u0 >> 32);
            ah[mt][1] = (uint32_t)u1; al[mt][1] = (uint32_t)(u1 >> 32);
            ah[mt][2] = (uint32_t)u2; al[mt][2] = (uint32_t)(u2 >> 32);
            ah[mt][3] = (uint32_t)u3; al[mt][3] = (uint32_t)(u3 >> 32);
        }

        // pass 1: Ah*Bl
#pragma unroll
        for (int mt = 0; mt < 4; mt++)
#pragma unroll
            for (int nt = 0; nt < 4; nt++)
                MMA_TF32_K8(acc[mt][nt], ah[mt][0], ah[mt][1], ah[mt][2], ah[mt][3],
                            bl[nt][0], bl[nt][1]);
        // pass 2: Al*Bh
#pragma unroll
        for (int mt = 0; mt < 4; mt++)
#pragma unroll
            for (int nt = 0; nt < 4; nt++)
                MMA_TF32_K8(acc[mt][nt], al[mt][0], al[mt][1], al[mt][2], al[mt][3],
                            bh[nt][0], bh[nt][1]);
        // pass 3: Ah*Bh
#pragma unroll
        for (int mt = 0; mt < 4; mt++)
#pragma unroll
            for (int nt = 0; nt < 4; nt++)
                MMA_TF32_K8(acc[mt][nt], ah[mt][0], ah[mt][1], ah[mt][2], ah[mt][3],
                            bh[nt][0], bh[nt][1]);

        if (hasnext) {
            int nb = buf ^ 1;
            Ab[nb][lc + 0][lr] = a01.x; Ab[nb][lc + 1][lr] = a01.y;
            Ab[nb][lc + 2][lr] = a23.x; Ab[nb][lc + 3][lr] = a23.y;
            if (TB) {
                Bb[nb][lc + 0][lr] = b01.x; Bb[nb][lc + 1][lr] = b01.y;
                Bb[nb][lc + 2][lr] = b23.x; Bb[nb][lc + 3][lr] = b23.y;
            } else {
                *(ulonglong2*)&Bb[nb][br][bc]     = b01;
                *(ulonglong2*)&Bb[nb][br][bc + 2] = b23;
            }
        }
        __syncthreads();
        buf ^= 1;
    }

    // epilogue: c0=(g,2t) c1=(g,2t+1) c2=(g+8,2t) c3=(g+8,2t+1)
#pragma unroll
    for (int mt = 0; mt < 4; mt++) {
        int row = m0 + mbase + mt * 16 + g;
#pragma unroll
        for (int nt = 0; nt < 4; nt++) {
            int col = n0 + nbase + nt * 8 + 2 * t;
            float b0 = bias ? __ldg(&bias[col])     : 0.f;
            float b1 = bias ? __ldg(&bias[col + 1]) : 0.f;
            float2 v0 = make_float2(alpha * acc[mt][nt][0] + b0,
                                    alpha * acc[mt][nt][1] + b1);
            float2 v1 = make_float2(alpha * acc[mt][nt][2] + b0,
                                    alpha * acc[mt][nt][3] + b1);
            *(float2*)&C[(size_t)row * N + col]       = v0;
            *(float2*)&C[(size_t)(row + 8) * N + col] = v1;
        }
    }
}

// ---------------- GRU recurrence: cluster of 16 CTAs per direction ----------------
// (round-7 form — measured best; FROZEN, register-cliff sensitive)
struct RecW {
    const float* Whh[4];
    const float* bhh[4];
};

__global__ void __launch_bounds__(512, 1) rec_kernel(RecW rw) {
    int dir  = blockIdx.x >> 4;
    int rank = blockIdx.x & (CLN - 1);
    int tid  = threadIdx.x;
    int lane = tid & 31, w = tid >> 5;   // 16 warps
    int hbase = rank * 32;

    __shared__ float hbuf[2][H_DIM];
    __shared__ float gs[96];

    ull wreg[6][8];
    {
        const float* Whh = rw.Whh[dir];
#pragma unroll
        for (int j = 0; j < 6; j++) {
            int m = w * 6 + j;
            int g = m >> 5, i = m & 31;
            const float* row = Whh + (size_t)(g * H_DIM + hbase + i) * H_DIM + 2 * lane;
#pragma unroll
            for (int p = 0; p < 8; p++)
                wreg[j][p] = *(const ull*)(row + 64 * p);
        }
    }
    float bhr = rw.bhh[dir][hbase + lane];
    float bhz = rw.bhh[dir][H_DIM + hbase + lane];
    float bhn = rw.bhh[dir][2 * H_DIM + hbase + lane];

    if (tid < H_DIM) hbuf[0][tid] = 0.f;

    uint32_t st0 = mapa_rank(smem_u32(&hbuf[0][hbase + lane]), (uint32_t)w);
    uint32_t st1 = mapa_rank(smem_u32(&hbuf[1][hbase + lane]), (uint32_t)w);

    CLUSTER_BAR();

    int fwd = !(dir & 1);
    const float* gx = g_gx[dir];
    float* feat = g_feat[dir >> 1];
    int foff = fwd ? 0 : H_DIM;

    for (int s = 0; s < S_LEN; s++) {
        int t = fwd ? s : (S_LEN - 1 - s);

        const float* gxp = gx + (size_t)t * G3 + hbase + lane;
        float gxr = __ldg(gxp);
        float gxz = __ldg(gxp + H_DIM);
        float gxn = __ldg(gxp + 2 * H_DIM);

        const float* hc = hbuf[s & 1];
        ull acc[6];
#pragma unroll
        for (int j = 0; j < 6; j++) acc[j] = 0ull;
#pragma unroll
        for (int p = 0; p < 8; p++) {
            ull hh = *(const ull*)&hc[64 * p + 2 * lane];
#pragma unroll
            for (int j = 0; j < 6; j++)
                asm("fma.rn.f32x2 %0, %1, %2, %0;" : "+l"(acc[j]) : "l"(wreg[j][p]), "l"(hh));
        }
#pragma unroll
        for (int j = 0; j < 6; j++) {
            float2 a2 = *(float2*)&acc[j];
            float v = a2.x + a2.y;
#pragma unroll
            for (int o = 16; o > 0; o >>= 1) v += __shfl_down_sync(0xffffffffu, v, o);
            if (lane == 0) gs[w * 6 + j] = v;
        }
        __syncthreads();

        float hold = hc[hbase + lane];
        float rg = fsig(gxr + gs[lane]      + bhr);
        float zg = fsig(gxz + gs[32 + lane] + bhz);
        float ng = ftanh(gxn + rg * (gs[64 + lane] + bhn));
        float hnew = (1.f - zg) * ng + zg * hold;

        st_cluster_f32((s & 1) ? st0 : st1, hnew);
        CLUSTER_ARRIVE();
        if (w == 0) feat[(size_t)t * F2 + foff + hbase + lane] = hnew;
        CLUSTER_WAIT();
    }
}

// ---------------- row softmax over 2048 cols (optional diagonal mask) ----------------
__global__ void __launch_bounds__(256) softmax_kernel(float* Mx, int mask_diag) {
    int row = blockIdx.x, tid = threadIdx.x;
    int lane = tid & 31, w = tid >> 5;
    float* rp = Mx + (size_t)row * S_LEN;
    float v[8];
    float4 a  = *(float4*)&rp[tid * 8];
    float4 b2 = *(float4*)&rp[tid * 8 + 4];
    v[0] = a.x;  v[1] = a.y;  v[2] = a.z;  v[3] = a.w;
    v[4] = b2.x; v[5] = b2.y; v[6] = b2.z; v[7] = b2.w;
    if (mask_diag) {
        int base = tid * 8;
#pragma unroll
        for (int u = 0; u < 8; u++)
            if (base + u == row) v[u] = -INFINITY;
    }
    __shared__ float red[8];
    float m = v[0];
#pragma unroll
    for (int u = 1; u < 8; u++) m = fmaxf(m, v[u]);
    m = warp_max(m);
    if (lane == 0) red[w] = m;
    __syncthreads();
    if (w == 0) {
        float t2 = (lane < 8) ? red[lane] : -INFINITY;
        t2 = warp_max(t2);
        if (lane == 0) red[0] = t2;
    }
    __syncthreads();
    float mx = red[0];
    __syncthreads();
    float s = 0.f;
#pragma unroll
    for (int u = 0; u < 8; u++) { v[u] = __expf(v[u] - mx); s += v[u]; }
    s = warp_sum(s);
    if (lane == 0) red[w] = s;
    __syncthreads();
    if (w == 0) {
        float t2 = (lane < 8) ? red[lane] : 0.f;
        t2 = warp_sum(t2);
        if (lane == 0) red[0] = t2;
    }
    __syncthreads();
    float inv = __fdividef(1.f, red[0]);
    float4 oa = make_float4(v[0] * inv, v[1] * inv, v[2] * inv, v[3] * inv);
    float4 ob = make_float4(v[4] * inv, v[5] * inv, v[6] * inv, v[7] * inv);
    *(float4*)&rp[tid * 8]     = oa;
    *(float4*)&rp[tid * 8 + 4] = ob;
}

// ---------------- emit ----------------
__global__ void __launch_bounds__(256) emit_kernel(
    const float* __restrict__ Wemit, const float* __restrict__ bemit)
{
    int t = blockIdx.x, tid = threadIdx.x;
    int lane = tid & 31, w = tid >> 5;
    const float* tg = &g_feat[1][(size_t)t * F2];
    const float* cx = &g_ctx2[0][(size_t)t * F2];
    const float* sc = &g_ctx2[1][(size_t)t * F2];
    float a0 = 0.f, a1 = 0.f;
    for (int u = tid; u < 3 * F2; u += 256) {
        float f = (u < F2) ? tg[u] : ((u < 2 * F2) ? cx[u - F2] : sc[u - 2 * F2]);
        a0 = fmaf(f, __ldg(&Wemit[u]), a0);
        a1 = fmaf(f, __ldg(&Wemit[3 * F2 + u]), a1);
    }
    __shared__ float r0[8], r1[8];
    a0 = warp_sum(a0); a1 = warp_sum(a1);
    if (lane == 0) { r0[w] = a0; r1[w] = a1; }
    __syncthreads();
    if (tid == 0) {
        float s0 = 0.f, s1 = 0.f;
        for (int i = 0; i < 8; i++) { s0 += r0[i]; s1 += r1[i]; }
        g_emit[t * 2 + 0] = s0 + __ldg(&bemit[0]);
        g_emit[t * 2 + 1] = s1 + __ldg(&bemit[1]);
    }
}

// ---------------- CRF ----------------
__global__ void __launch_bounds__(256) crf_kernel(
    const int* __restrict__ labels, const float* __restrict__ t_start,
    const float* __restrict__ t_trans, const float* __restrict__ t_end,
    float* __restrict__ out)
{
    __shared__ float se[S_LEN * 2];
    __shared__ float red[8];
    int tid = threadIdx.x;
    int lane = tid & 31, w = tid >> 5;
    for (int i = tid; i < S_LEN * 2; i += 256) se[i] = g_emit[i];

    float gsum = 0.f;
    for (int t = tid; t < S_LEN; t += 256) {
        int l = __ldg(&labels[t]);
        gsum += g_emit[t * 2 + l];
        if (t > 0) gsum += __ldg(&t_trans[l * 2 + __ldg(&labels[t - 1])]);
    }
    gsum = warp_sum(gsum);
    if (lane == 0) red[w] = gsum;
    __syncthreads();

    if (tid == 0) {
        float gold = 0.f;
        for (int i = 0; i < 8; i++) gold += red[i];
        gold += __ldg(&t_start[__ldg(&labels[0])]) + __ldg(&t_end[__ldg(&labels[S_LEN - 1])]);

        float tt00 = __ldg(&t_trans[0]), tt01 = __ldg(&t_trans[1]);
        float tt10 = __ldg(&t_trans[2]), tt11 = __ldg(&t_trans[3]);
        float a0 = __ldg(&t_start[0]) + se[0];
        float a1 = __ldg(&t_start[1]) + se[1];
        for (int t = 1; t < S_LEN; t++) {
            float n0 = lse2(tt00 + a0, tt01 + a1) + se[t * 2];
            float n1 = lse2(tt10 + a0, tt11 + a1) + se[t * 2 + 1];
            a0 = n0; a1 = n1;
        }
        float logZ = lse2(__ldg(&t_end[0]) + a0, __ldg(&t_end[1]) + a1);
        out[0] = gold - logZ;
    }
}

// ---------------- launch ----------------
extern "C" void kernel_launch(void* const* d_in, const int* in_sizes, int n_in,
                              void* d_out, int out_size)
{
    (void)in_sizes; (void)n_in; (void)out_size;
    const float* source = (const float*)d_in[0];
    const float* target = (const float*)d_in[1];
    const int*   labels = (const int*)d_in[2];

    const float* Wih[4] = { (const float*)d_in[3],  (const float*)d_in[7],
                            (const float*)d_in[11], (const float*)d_in[15] };
    const float* Whh[4] = { (const float*)d_in[4],  (const float*)d_in[8],
                            (const float*)d_in[12], (const float*)d_in[16] };
    const float* bih[4] = { (const float*)d_in[5],  (const float*)d_in[9],
                            (const float*)d_in[13], (const float*)d_in[17] };
    const float* bhh[4] = { (const float*)d_in[6],  (const float*)d_in[10],
                            (const float*)d_in[14], (const float*)d_in[18] };
    const float* Wemit  = (const float*)d_in[19];
    const float* bemit  = (const float*)d_in[20];
    const float* tstart = (const float*)d_in[21];
    const float* ttrans = (const float*)d_in[22];
    const float* tend   = (const float*)d_in[23];

    float *p_gx, *p_feat, *p_attn, *p_ctx;
    ull *p_sxt, *p_swih, *p_sfeat, *p_sattn;
    cudaGetSymbolAddress((void**)&p_gx,    g_gx);
    cudaGetSymbolAddress((void**)&p_feat,  g_feat);
    cudaGetSymbolAddress((void**)&p_attn,  g_attn);
    cudaGetSymbolAddress((void**)&p_ctx,   g_ctx2);
    cudaGetSymbolAddress((void**)&p_sxt,   g_sxt);
    cudaGetSymbolAddress((void**)&p_swih,  g_swih);
    cudaGetSymbolAddress((void**)&p_sfeat, g_sfeat);
    cudaGetSymbolAddress((void**)&p_sattn, g_sattn);

    float* srcf = p_feat;
    float* tgtf = p_feat + (size_t)S_LEN * F2;
    float* alig = p_attn;
    float* sali = p_attn + (size_t)S_LEN * S_LEN;
    float* ctx  = p_ctx;
    float* sctx = p_ctx + (size_t)S_LEN * F2;

    // pre-split gx operands
    {
        int nx = S_LEN * E_DIM;
        split_kernel<<<nx / 4 / 256, 256>>>(source, p_sxt, nx);
        split_kernel<<<nx / 4 / 256, 256>>>(target, p_sxt + nx, nx);
        int nw = G3 * E_DIM;
        for (int d = 0; d < 4; d++)
            split_kernel<<<nw / 4 / 256, 256>>>(Wih[d], p_swih + (size_t)d * nw, nw);
    }

    // gx[dir] = x @ Wih^T + bih  (M=2048, N=1536, K=512), 3xTF32 TC, batched
    {
        GemmBatch4 bt;
        for (int d = 0; d < 4; d++) {
            bt.g[d].A = p_sxt + (size_t)(d < 2 ? 0 : 1) * S_LEN * E_DIM;
            bt.g[d].B = p_swih + (size_t)d * G3 * E_DIM;
            bt.g[d].C = p_gx + (size_t)d * S_LEN * G3;
            bt.g[d].bias = bih[d];
        }
        tf32gemm_kernel<1><<<dim3(G3 / 128, S_LEN / 128, 4), 256>>>(
            bt, S_LEN, G3, E_DIM, 1.f);
    }

    // recurrence: 4 clusters of 16 CTAs
    RecW rw;
    for (int d = 0; d < 4; d++) { rw.Whh[d] = Whh[d]; rw.bhh[d] = bhh[d]; }
    cudaFuncSetAttribute(rec_kernel, cudaFuncAttributeNonPortableClusterSizeAllowed, 1);
    {
        cudaLaunchConfig_t cfg = {};
        cfg.gridDim = dim3(4 * CLN, 1, 1);
        cfg.blockDim = dim3(512, 1, 1);
        cfg.dynamicSmemBytes = 0;
        cfg.stream = 0;
        cudaLaunchAttribute attrs[1];
        attrs[0].id = cudaLaunchAttributeClusterDimension;
        attrs[0].val.clusterDim = {CLN, 1, 1};
        cfg.attrs = attrs;
        cfg.numAttrs = 1;
        cudaLaunchKernelEx(&cfg, rec_kernel, rw);
    }

    // split feat (both halves contiguous)
    {
        int nf = 2 * S_LEN * F2;
        split_kernel<<<nf / 4 / 256, 256>>>(p_feat, p_sfeat, nf);
    }
    const ull* ssrcf = p_sfeat;
    const ull* stgtf = p_sfeat + (size_t)S_LEN * F2;

    // align = (tgt_f @ src_f^T) * 32 ; s_align = (tgt_f @ tgt_f^T) * 32  (3xTF32 TC)
    {
        GemmBatch4 bt;
        bt.g[0] = { stgtf, ssrcf, alig, nullptr };
        bt.g[1] = { stgtf, stgtf, sali, nullptr };
        bt.g[2] = bt.g[0]; bt.g[3] = bt.g[0];
        tf32gemm_kernel<1><<<dim3(S_LEN / 128, S_LEN / 128, 2), 256>>>(
            bt, S_LEN, S_LEN, F2, 32.f);
    }

    softmax_kernel<<<S_LEN, 256>>>(alig, 0);
    softmax_kernel<<<S_LEN, 256>>>(sali, 1);

    // split softmaxed attention (both matrices contiguous)
    {
        int na = 2 * S_LEN * S_LEN;
        split_kernel<<<na / 4 / 256, 256>>>(p_attn, p_sattn, na);
    }
    const ull* salig = p_sattn;
    const ull* ssali = p_sattn + (size_t)S_LEN * S_LEN;

    // context = P @ src_f ; s_context = Ps @ tgt_f  (3xTF32 TC)
    {
        GemmBatch4 bt;
        bt.g[0] = { salig, ssrcf, ctx,  nullptr };
        bt.g[1] = { ssali, stgtf, sctx, nullptr };
        bt.g[2] = bt.g[0]; bt.g[3] = bt.g[0];
        tf32gemm_kernel<0><<<dim3(F2 / 128, S_LEN / 128, 2), 256>>>(
            bt, S_LEN, F2, S_LEN, 1.f);
    }

    emit_kernel<<<S_LEN, 256>>>(Wemit, bemit);
    crf_kernel<<<1, 256>>>(labels, tstart, ttrans, tend, (float*)d_out);
}

// round 16
// speedup vs baseline: 1.1979x; 1.1979x over previous
#include <cuda_runtime.h>
#include <cuda_bf16.h>
#include <math.h>
#include <stdint.h>

#define S_LEN 2048
#define E_DIM 512
#define H_DIM 512
#define G3    1536   // 3*H
#define F2    1024   // 2*H
#define CLN   16     // CTAs per direction (one cluster)
#define TFS   132    // smem row stride in ull (conflict-free frag loads)

typedef unsigned long long ull;

// ---------------- device scratch (static; no allocations) ----------------
__device__ float g_gx[4][S_LEN * G3];
__device__ float g_feat[2][S_LEN * F2];      // 0: src bi-feat, 1: tgt bi-feat
__device__ float g_attn[2][S_LEN * S_LEN];   // 0: cross align, 1: self align
__device__ float g_ctx2[2][S_LEN * F2];      // 0: context, 1: s_context
__device__ float g_emit[S_LEN * 2];

// ---------------- helpers ----------------
__device__ __forceinline__ uint32_t smem_u32(const void* p) {
    uint32_t a;
    asm("{ .reg .u64 t; cvta.to.shared.u64 t, %1; cvt.u32.u64 %0, t; }" : "=r"(a) : "l"(p));
    return a;
}
__device__ __forceinline__ uint32_t mapa_rank(uint32_t laddr, uint32_t rank) {
    uint32_t r;
    asm("mapa.shared::cluster.u32 %0, %1, %2;" : "=r"(r) : "r"(laddr), "r"(rank));
    return r;
}
__device__ __forceinline__ void st_cluster_f32(uint32_t addr, float v) {
    asm volatile("st.shared::cluster.f32 [%0], %1;" :: "r"(addr), "f"(v) : "memory");
}
#define CLUSTER_ARRIVE() asm volatile("barrier.cluster.arrive.aligned;" ::: "memory")
#define CLUSTER_WAIT()   asm volatile("barrier.cluster.wait.aligned;" ::: "memory")
#define CLUSTER_BAR() do { CLUSTER_ARRIVE(); CLUSTER_WAIT(); } while (0)

__device__ __forceinline__ float warp_max(float x) {
#pragma unroll
    for (int o = 16; o > 0; o >>= 1) x = fmaxf(x, __shfl_xor_sync(0xffffffffu, x, o));
    return x;
}
__device__ __forceinline__ float warp_sum(float x) {
#pragma unroll
    for (int o = 16; o > 0; o >>= 1) x += __shfl_xor_sync(0xffffffffu, x, o);
    return x;
}
__device__ __forceinline__ float fsig(float x) {
    return __fdividef(1.f, 1.f + __expf(-x));
}
__device__ __forceinline__ float ftanh(float x) {
    float t = __expf(2.f * x);
    return 1.f - __fdividef(2.f, t + 1.f);
}
__device__ __forceinline__ float lse2(float a, float b) {
    float m = fmaxf(a, b);
    float d = fminf(a, b) - m;
    return m + __logf(1.f + __expf(d));
}
// bf16 3-term split of a k-pair (v0 = even k, v1 = odd k):
// returns (hipair bf16x2) in low u32, (lopair bf16x2) in high u32.
// bf16x2 packing: even-k in lower 16 bits (MMA element order).
__device__ __forceinline__ ull split_bf16_pair(float v0, float v1) {
    float h0, h1;
    asm("{.reg .b16 t; cvt.rn.bf16.f32 t, %1; cvt.f32.bf16 %0, t;}" : "=f"(h0) : "f"(v0));
    asm("{.reg .b16 t; cvt.rn.bf16.f32 t, %1; cvt.f32.bf16 %0, t;}" : "=f"(h1) : "f"(v1));
    uint32_t hp, lp;
    asm("cvt.rn.bf16x2.f32 %0, %1, %2;" : "=r"(hp) : "f"(h1), "f"(h0));
    float l0 = v0 - h0, l1 = v1 - h1;
    asm("cvt.rn.bf16x2.f32 %0, %1, %2;" : "=r"(lp) : "f"(l1), "f"(l0));
    return (ull)hp | ((ull)lp << 32);
}
#define MMA_BF16_K16(d, A0, A1, A2, A3, B0, B1) \
    asm("mma.sync.aligned.m16n8k16.row.col.f32.bf16.bf16.f32 " \
        "{%0,%1,%2,%3}, {%4,%5,%6,%7}, {%8,%9}, {%0,%1,%2,%3};" \
        : "+f"((d)[0]), "+f"((d)[1]), "+f"((d)[2]), "+f"((d)[3]) \
        : "r"(A0), "r"(A1), "r"(A2), "r"(A3), "r"(B0), "r"(B1))

// ---------------- batched 3xBF16 tensor-core GEMM (m16n8k16) ----------------
// C[M,N] = alpha * A[M,K] * op(B) (+ bias[n]). TB=1: B is [N,K]; TB=0: [K,N].
// acc += Ah*Bl + Al*Bh + Ah*Bh (~2^-17 product precision, fp32 accumulate).
// CTA 128x128, 8 warps (2Mx4N), warp tile 64x32, double-buffered smem,
// in-loop split packed as (hipair,lopair) ull per (k-pair,row). K % 16 == 0.
struct GemmEnt { const float* A; const float* B; float* C; const float* bias; };
struct GemmBatch4 { GemmEnt g[4]; };

template <int TB>
__global__ void __launch_bounds__(256, 1) bf16gemm_kernel(
    GemmBatch4 bt, int M, int N, int K, float alpha)
{
    const float* __restrict__ A    = bt.g[blockIdx.z].A;
    const float* __restrict__ B    = bt.g[blockIdx.z].B;
    float* __restrict__ C          = bt.g[blockIdx.z].C;
    const float* __restrict__ bias = bt.g[blockIdx.z].bias;

    __shared__ ull Ab[2][8][TFS];   // [kpair 0..7][row]
    __shared__ ull Bb[2][8][TFS];   // [kpair 0..7][col]

    int tid  = threadIdx.x;
    int lane = tid & 31, w = tid >> 5;
    int g = lane >> 2, t = lane & 3;
    int mbase = (w >> 2) * 64;
    int nbase = (w & 3) * 32;
    int m0 = blockIdx.y * 128, n0 = blockIdx.x * 128;

    float acc[4][4][4];
#pragma unroll
    for (int mt = 0; mt < 4; mt++)
#pragma unroll
        for (int nt = 0; nt < 4; nt++)
#pragma unroll
            for (int q = 0; q < 4; q++) acc[mt][nt][q] = 0.f;

    int lr  = tid >> 1;            // 0..127
    int lc4 = (tid & 1) * 4;       // 0 or 4 (k-cols lc4..lc4+3 and lc4+8..lc4+11)
    int kp0 = lc4 >> 1;            // base k-pair: 0 or 2
    const float* Aptr = A + (size_t)(m0 + lr) * K + lc4;
    const float *Bp0, *Bp1;
    int bq = tid >> 5;             // 0..7 k-pair row (TB=0)
    int bc = (tid & 31) << 2;      // col (TB=0)
    if (TB) { Bp0 = B + (size_t)(n0 + lr) * K + lc4; Bp1 = Bp0; }
    else    { Bp0 = B + (size_t)(2 * bq) * N + n0 + bc; Bp1 = Bp0 + N; }

    // preload tile 0
    {
        float4 a0 = *(const float4*)(Aptr);
        float4 a1 = *(const float4*)(Aptr + 8);
        Ab[0][kp0 + 0][lr] = split_bf16_pair(a0.x, a0.y);
        Ab[0][kp0 + 1][lr] = split_bf16_pair(a0.z, a0.w);
        Ab[0][kp0 + 4][lr] = split_bf16_pair(a1.x, a1.y);
        Ab[0][kp0 + 5][lr] = split_bf16_pair(a1.z, a1.w);
        if (TB) {
            float4 b0 = *(const float4*)(Bp0);
            float4 b1 = *(const float4*)(Bp0 + 8);
            Bb[0][kp0 + 0][lr] = split_bf16_pair(b0.x, b0.y);
            Bb[0][kp0 + 1][lr] = split_bf16_pair(b0.z, b0.w);
            Bb[0][kp0 + 4][lr] = split_bf16_pair(b1.x, b1.y);
            Bb[0][kp0 + 5][lr] = split_bf16_pair(b1.z, b1.w);
        } else {
            float4 b0 = *(const float4*)(Bp0);
            float4 b1 = *(const float4*)(Bp1);
            Bb[0][bq][bc + 0] = split_bf16_pair(b0.x, b1.x);
            Bb[0][bq][bc + 1] = split_bf16_pair(b0.y, b1.y);
            Bb[0][bq][bc + 2] = split_bf16_pair(b0.z, b1.z);
            Bb[0][bq][bc + 3] = split_bf16_pair(b0.w, b1.w);
        }
    }
    __syncthreads();

    int buf = 0;
    for (int k0 = 0; k0 < K; k0 += 16) {
        bool hasnext = (k0 + 16 < K);
        float4 an0, an1, bn0, bn1;
        if (hasnext) {
            an0 = *(const float4*)(Aptr + k0 + 16);
            an1 = *(const float4*)(Aptr + k0 + 24);
            if (TB) {
                bn0 = *(const float4*)(Bp0 + k0 + 16);
                bn1 = *(const float4*)(Bp0 + k0 + 24);
            } else {
                bn0 = *(const float4*)(Bp0 + (size_t)(k0 + 16) * N);
                bn1 = *(const float4*)(Bp1 + (size_t)(k0 + 16) * N);
            }
        }

        // hoist fragments: a0=(g,kp t) a1=(g+8,kp t) a2=(g,kp t+4) a3=(g+8,kp t+4)
        uint32_t ah[4][4], al[4][4], bh[4][2], bl[4][2];
#pragma unroll
        for (int nt = 0; nt < 4; nt++) {
            int c = nbase + nt * 8 + g;
            ull v0 = Bb[buf][t][c];
            ull v1 = Bb[buf][t + 4][c];
            bh[nt][0] = (uint32_t)v0; bl[nt][0] = (uint32_t)(v0 >> 32);
            bh[nt][1] = (uint32_t)v1; bl[nt][1] = (uint32_t)(v1 >> 32);
        }
#pragma unroll
        for (int mt = 0; mt < 4; mt++) {
            int r = mbase + mt * 16 + g;
            ull u0 = Ab[buf][t][r];
            ull u1 = Ab[buf][t][r + 8];
            ull u2 = Ab[buf][t + 4][r];
            ull u3 = Ab[buf][t + 4][r + 8];
            ah[mt][0] = (uint32_t)u0; al[mt][0] = (uint32_t)(u0 >> 32);
            ah[mt][1] = (uint32_t)u1; al[mt][1] = (uint32_t)(u1 >> 32);
            ah[mt][2] = (uint32_t)u2; al[mt][2] = (uint32_t)(u2 >> 32);
            ah[mt][3] = (uint32_t)u3; al[mt][3] = (uint32_t)(u3 >> 32);
        }

        // pass 1: Ah*Bl
#pragma unroll
        for (int mt = 0; mt < 4; mt++)
#pragma unroll
            for (int nt = 0; nt < 4; nt++)
                MMA_BF16_K16(acc[mt][nt], ah[mt][0], ah[mt][1], ah[mt][2], ah[mt][3],
                             bl[nt][0], bl[nt][1]);
        // pass 2: Al*Bh
#pragma unroll
        for (int mt = 0; mt < 4; mt++)
#pragma unroll
            for (int nt = 0; nt < 4; nt++)
                MMA_BF16_K16(acc[mt][nt], al[mt][0], al[mt][1], al[mt][2], al[mt][3],
                             bh[nt][0], bh[nt][1]);
        // pass 3: Ah*Bh
#pragma unroll
        for (int mt = 0; mt < 4; mt++)
#pragma unroll
            for (int nt = 0; nt < 4; nt++)
                MMA_BF16_K16(acc[mt][nt], ah[mt][0], ah[mt][1], ah[mt][2], ah[mt][3],
                             bh[nt][0], bh[nt][1]);

        if (hasnext) {
            int nb = buf ^ 1;
            Ab[nb][kp0 + 0][lr] = split_bf16_pair(an0.x, an0.y);
            Ab[nb][kp0 + 1][lr] = split_bf16_pair(an0.z, an0.w);
            Ab[nb][kp0 + 4][lr] = split_bf16_pair(an1.x, an1.y);
            Ab[nb][kp0 + 5][lr] = split_bf16_pair(an1.z, an1.w);
            if (TB) {
                Bb[nb][kp0 + 0][lr] = split_bf16_pair(bn0.x, bn0.y);
                Bb[nb][kp0 + 1][lr] = split_bf16_pair(bn0.z, bn0.w);
                Bb[nb][kp0 + 4][lr] = split_bf16_pair(bn1.x, bn1.y);
                Bb[nb][kp0 + 5][lr] = split_bf16_pair(bn1.z, bn1.w);
            } else {
                Bb[nb][bq][bc + 0] = split_bf16_pair(bn0.x, bn1.x);
                Bb[nb][bq][bc + 1] = split_bf16_pair(bn0.y, bn1.y);
                Bb[nb][bq][bc + 2] = split_bf16_pair(bn0.z, bn1.z);
                Bb[nb][bq][bc + 3] = split_bf16_pair(bn0.w, bn1.w);
            }
        }
        __syncthreads();
        buf ^= 1;
    }

    // epilogue: c0=(g,2t) c1=(g,2t+1) c2=(g+8,2t) c3=(g+8,2t+1)
#pragma unroll
    for (int mt = 0; mt < 4; mt++) {
        int row = m0 + mbase + mt * 16 + g;
#pragma unroll
        for (int nt = 0; nt < 4; nt++) {
            int col = n0 + nbase + nt * 8 + 2 * t;
            float b0 = bias ? __ldg(&bias[col])     : 0.f;
            float b1 = bias ? __ldg(&bias[col + 1]) : 0.f;
            float2 v0 = make_float2(alpha * acc[mt][nt][0] + b0,
                                    alpha * acc[mt][nt][1] + b1);
            float2 v1 = make_float2(alpha * acc[mt][nt][2] + b0,
                                    alpha * acc[mt][nt][3] + b1);
            *(float2*)&C[(size_t)row * N + col]       = v0;
            *(float2*)&C[(size_t)(row + 8) * N + col] = v1;
        }
    }
}

// ---------------- GRU recurrence: cluster of 16 CTAs per direction ----------------
// (round-7 form — measured best; FROZEN, register-cliff sensitive)
struct RecW {
    const float* Whh[4];
    const float* bhh[4];
};

__global__ void __launch_bounds__(512, 1) rec_kernel(RecW rw) {
    int dir  = blockIdx.x >> 4;
    int rank = blockIdx.x & (CLN - 1);
    int tid  = threadIdx.x;
    int lane = tid & 31, w = tid >> 5;   // 16 warps
    int hbase = rank * 32;

    __shared__ float hbuf[2][H_DIM];
    __shared__ float gs[96];

    ull wreg[6][8];
    {
        const float* Whh = rw.Whh[dir];
#pragma unroll
        for (int j = 0; j < 6; j++) {
            int m = w * 6 + j;
            int g = m >> 5, i = m & 31;
            const float* row = Whh + (size_t)(g * H_DIM + hbase + i) * H_DIM + 2 * lane;
#pragma unroll
            for (int p = 0; p < 8; p++)
                wreg[j][p] = *(const ull*)(row + 64 * p);
        }
    }
    float bhr = rw.bhh[dir][hbase + lane];
    float bhz = rw.bhh[dir][H_DIM + hbase + lane];
    float bhn = rw.bhh[dir][2 * H_DIM + hbase + lane];

    if (tid < H_DIM) hbuf[0][tid] = 0.f;

    uint32_t st0 = mapa_rank(smem_u32(&hbuf[0][hbase + lane]), (uint32_t)w);
    uint32_t st1 = mapa_rank(smem_u32(&hbuf[1][hbase + lane]), (uint32_t)w);

    CLUSTER_BAR();

    int fwd = !(dir & 1);
    const float* gx = g_gx[dir];
    float* feat = g_feat[dir >> 1];
    int foff = fwd ? 0 : H_DIM;

    for (int s = 0; s < S_LEN; s++) {
        int t = fwd ? s : (S_LEN - 1 - s);

        const float* gxp = gx + (size_t)t * G3 + hbase + lane;
        float gxr = __ldg(gxp);
        float gxz = __ldg(gxp + H_DIM);
        float gxn = __ldg(gxp + 2 * H_DIM);

        const float* hc = hbuf[s & 1];
        ull acc[6];
#pragma unroll
        for (int j = 0; j < 6; j++) acc[j] = 0ull;
#pragma unroll
        for (int p = 0; p < 8; p++) {
            ull hh = *(const ull*)&hc[64 * p + 2 * lane];
#pragma unroll
            for (int j = 0; j < 6; j++)
                asm("fma.rn.f32x2 %0, %1, %2, %0;" : "+l"(acc[j]) : "l"(wreg[j][p]), "l"(hh));
        }
#pragma unroll
        for (int j = 0; j < 6; j++) {
            float2 a2 = *(float2*)&acc[j];
            float v = a2.x + a2.y;
#pragma unroll
            for (int o = 16; o > 0; o >>= 1) v += __shfl_down_sync(0xffffffffu, v, o);
            if (lane == 0) gs[w * 6 + j] = v;
        }
        __syncthreads();

        float hold = hc[hbase + lane];
        float rg = fsig(gxr + gs[lane]      + bhr);
        float zg = fsig(gxz + gs[32 + lane] + bhz);
        float ng = ftanh(gxn + rg * (gs[64 + lane] + bhn));
        float hnew = (1.f - zg) * ng + zg * hold;

        st_cluster_f32((s & 1) ? st0 : st1, hnew);
        CLUSTER_ARRIVE();
        if (w == 0) feat[(size_t)t * F2 + foff + hbase + lane] = hnew;
        CLUSTER_WAIT();
    }
}

// ---------------- row softmax over 2048 cols (optional diagonal mask) ----------------
__global__ void __launch_bounds__(256) softmax_kernel(float* Mx, int mask_diag) {
    int row = blockIdx.x, tid = threadIdx.x;
    int lane = tid & 31, w = tid >> 5;
    float* rp = Mx + (size_t)row * S_LEN;
    float v[8];
    float4 a  = *(float4*)&rp[tid * 8];
    float4 b2 = *(float4*)&rp[tid * 8 + 4];
    v[0] = a.x;  v[1] = a.y;  v[2] = a.z;  v[3] = a.w;
    v[4] = b2.x; v[5] = b2.y; v[6] = b2.z; v[7] = b2.w;
    if (mask_diag) {
        int base = tid * 8;
#pragma unroll
        for (int u = 0; u < 8; u++)
            if (base + u == row) v[u] = -INFINITY;
    }
    __shared__ float red[8];
    float m = v[0];
#pragma unroll
    for (int u = 1; u < 8; u++) m = fmaxf(m, v[u]);
    m = warp_max(m);
    if (lane == 0) red[w] = m;
    __syncthreads();
    if (w == 0) {
        float t2 = (lane < 8) ? red[lane] : -INFINITY;
        t2 = warp_max(t2);
        if (lane == 0) red[0] = t2;
    }
    __syncthreads();
    float mx = red[0];
    __syncthreads();
    float s = 0.f;
#pragma unroll
    for (int u = 0; u < 8; u++) { v[u] = __expf(v[u] - mx); s += v[u]; }
    s = warp_sum(s);
    if (lane == 0) red[w] = s;
    __syncthreads();
    if (w == 0) {
        float t2 = (lane < 8) ? red[lane] : 0.f;
        t2 = warp_sum(t2);
        if (lane == 0) red[0] = t2;
    }
    __syncthreads();
    float inv = __fdividef(1.f, red[0]);
    float4 oa = make_float4(v[0] * inv, v[1] * inv, v[2] * inv, v[3] * inv);
    float4 ob = make_float4(v[4] * inv, v[5] * inv, v[6] * inv, v[7] * inv);
    *(float4*)&rp[tid * 8]     = oa;
    *(float4*)&rp[tid * 8 + 4] = ob;
}

// ---------------- emit ----------------
__global__ void __launch_bounds__(256) emit_kernel(
    const float* __restrict__ Wemit, const float* __restrict__ bemit)
{
    int t = blockIdx.x, tid = threadIdx.x;
    int lane = tid & 31, w = tid >> 5;
    const float* tg = &g_feat[1][(size_t)t * F2];
    const float* cx = &g_ctx2[0][(size_t)t * F2];
    const float* sc = &g_ctx2[1][(size_t)t * F2];
    float a0 = 0.f, a1 = 0.f;
    for (int u = tid; u < 3 * F2; u += 256) {
        float f = (u < F2) ? tg[u] : ((u < 2 * F2) ? cx[u - F2] : sc[u - 2 * F2]);
        a0 = fmaf(f, __ldg(&Wemit[u]), a0);
        a1 = fmaf(f, __ldg(&Wemit[3 * F2 + u]), a1);
    }
    __shared__ float r0[8], r1[8];
    a0 = warp_sum(a0); a1 = warp_sum(a1);
    if (lane == 0) { r0[w] = a0; r1[w] = a1; }
    __syncthreads();
    if (tid == 0) {
        float s0 = 0.f, s1 = 0.f;
        for (int i = 0; i < 8; i++) { s0 += r0[i]; s1 += r1[i]; }
        g_emit[t * 2 + 0] = s0 + __ldg(&bemit[0]);
        g_emit[t * 2 + 1] = s1 + __ldg(&bemit[1]);
    }
}

// ---------------- CRF ----------------
__global__ void __launch_bounds__(256) crf_kernel(
    const int* __restrict__ labels, const float* __restrict__ t_start,
    const float* __restrict__ t_trans, const float* __restrict__ t_end,
    float* __restrict__ out)
{
    __shared__ float se[S_LEN * 2];
    __shared__ float red[8];
    int tid = threadIdx.x;
    int lane = tid & 31, w = tid >> 5;
    for (int i = tid; i < S_LEN * 2; i += 256) se[i] = g_emit[i];

    float gsum = 0.f;
    for (int t = tid; t < S_LEN; t += 256) {
        int l = __ldg(&labels[t]);
        gsum += g_emit[t * 2 + l];
        if (t > 0) gsum += __ldg(&t_trans[l * 2 + __ldg(&labels[t - 1])]);
    }
    gsum = warp_sum(gsum);
    if (lane == 0) red[w] = gsum;
    __syncthreads();

    if (tid == 0) {
        float gold = 0.f;
        for (int i = 0; i < 8; i++) gold += red[i];
        gold += __ldg(&t_start[__ldg(&labels[0])]) + __ldg(&t_end[__ldg(&labels[S_LEN - 1])]);

        float tt00 = __ldg(&t_trans[0]), tt01 = __ldg(&t_trans[1]);
        float tt10 = __ldg(&t_trans[2]), tt11 = __ldg(&t_trans[3]);
        float a0 = __ldg(&t_start[0]) + se[0];
        float a1 = __ldg(&t_start[1]) + se[1];
        for (int t = 1; t < S_LEN; t++) {
            float n0 = lse2(tt00 + a0, tt01 + a1) + se[t * 2];
            float n1 = lse2(tt10 + a0, tt11 + a1) + se[t * 2 + 1];
            a0 = n0; a1 = n1;
        }
        float logZ = lse2(__ldg(&t_end[0]) + a0, __ldg(&t_end[1]) + a1);
        out[0] = gold - logZ;
    }
}

// ---------------- launch ----------------
extern "C" void kernel_launch(void* const* d_in, const int* in_sizes, int n_in,
                              void* d_out, int out_size)
{
    (void)in_sizes; (void)n_in; (void)out_size;
    const float* source = (const float*)d_in[0];
    const float* target = (const float*)d_in[1];
    const int*   labels = (const int*)d_in[2];

    const float* Wih[4] = { (const float*)d_in[3],  (const float*)d_in[7],
                            (const float*)d_in[11], (const float*)d_in[15] };
    const float* Whh[4] = { (const float*)d_in[4],  (const float*)d_in[8],
                            (const float*)d_in[12], (const float*)d_in[16] };
    const float* bih[4] = { (const float*)d_in[5],  (const float*)d_in[9],
                            (const float*)d_in[13], (const float*)d_in[17] };
    const float* bhh[4] = { (const float*)d_in[6],  (const float*)d_in[10],
                            (const float*)d_in[14], (const float*)d_in[18] };
    const float* Wemit  = (const float*)d_in[19];
    const float* bemit  = (const float*)d_in[20];
    const float* tstart = (const float*)d_in[21];
    const float* ttrans = (const float*)d_in[22];
    const float* tend   = (const float*)d_in[23];

    float *p_gx, *p_feat, *p_attn, *p_ctx;
    cudaGetSymbolAddress((void**)&p_gx,   g_gx);
    cudaGetSymbolAddress((void**)&p_feat, g_feat);
    cudaGetSymbolAddress((void**)&p_attn, g_attn);
    cudaGetSymbolAddress((void**)&p_ctx,  g_ctx2);

    float* srcf = p_feat;
    float* tgtf = p_feat + (size_t)S_LEN * F2;
    float* alig = p_attn;
    float* sali = p_attn + (size_t)S_LEN * S_LEN;
    float* ctx  = p_ctx;
    float* sctx = p_ctx + (size_t)S_LEN * F2;

    // gx[dir] = x @ Wih^T + bih  (M=2048, N=1536, K=512), 3xBF16 TC, batched
    {
        GemmBatch4 bt;
        for (int d = 0; d < 4; d++) {
            bt.g[d].A = (d < 2) ? source : target;
            bt.g[d].B = Wih[d];
            bt.g[d].C = p_gx + (size_t)d * S_LEN * G3;
            bt.g[d].bias = bih[d];
        }
        bf16gemm_kernel<1><<<dim3(G3 / 128, S_LEN / 128, 4), 256>>>(
            bt, S_LEN, G3, E_DIM, 1.f);
    }

    // recurrence: 4 clusters of 16 CTAs
    RecW rw;
    for (int d = 0; d < 4; d++) { rw.Whh[d] = Whh[d]; rw.bhh[d] = bhh[d]; }
    cudaFuncSetAttribute(rec_kernel, cudaFuncAttributeNonPortableClusterSizeAllowed, 1);
    {
        cudaLaunchConfig_t cfg = {};
        cfg.gridDim = dim3(4 * CLN, 1, 1);
        cfg.blockDim = dim3(512, 1, 1);
        cfg.dynamicSmemBytes = 0;
        cfg.stream = 0;
        cudaLaunchAttribute attrs[1];
        attrs[0].id = cudaLaunchAttributeClusterDimension;
        attrs[0].val.clusterDim = {CLN, 1, 1};
        cfg.attrs = attrs;
        cfg.numAttrs = 1;
        cudaLaunchKernelEx(&cfg, rec_kernel, rw);
    }

    // align = (tgt_f @ src_f^T) * 32 ; s_align = (tgt_f @ tgt_f^T) * 32  (3xBF16 TC)
    {
        GemmBatch4 bt;
        bt.g[0] = { tgtf, srcf, alig, nullptr };
        bt.g[1] = { tgtf, tgtf, sali, nullptr };
        bt.g[2] = bt.g[0]; bt.g[3] = bt.g[0];
        bf16gemm_kernel<1><<<dim3(S_LEN / 128, S_LEN / 128, 2), 256>>>(
            bt, S_LEN, S_LEN, F2, 32.f);
    }

    softmax_kernel<<<S_LEN, 256>>>(alig, 0);
    softmax_kernel<<<S_LEN, 256>>>(sali, 1);

    // context = P @ src_f ; s_context = Ps @ tgt_f  (3xBF16 TC)
    {
        GemmBatch4 bt;
        bt.g[0] = { alig, srcf, ctx,  nullptr };
        bt.g[1] = { sali, tgtf, sctx, nullptr };
        bt.g[2] = bt.g[0]; bt.g[3] = bt.g[0];
        bf16gemm_kernel<0><<<dim3(F2 / 128, S_LEN / 128, 2), 256>>>(
            bt, S_LEN, F2, S_LEN, 1.f);
    }

    emit_kernel<<<S_LEN, 256>>>(Wemit, bemit);
    crf_kernel<<<1, 256>>>(labels, tstart, ttrans, tend, (float*)d_out);
}